// round 4
// baseline (speedup 1.0000x reference)
#include <cuda_runtime.h>

#define NX 1024
#define NY 1024
#define NB 8
#define CH (NX*NY)
#define ROWS 16
#define STRIPS (NY/ROWS)        // 64
#define NBLOCKS (STRIPS*NB)     // 512
#define SMEM_BYTES (18*NX*4)    // 73728

// Physics constants
#define PR     0.71f
#define RA_PR  710.0f
#define HA2_PR 71.0f
#define PR_DA  7.1f
#define DIFF_C 1.6666666666666667f
#define QQ     0.1f
#define DTINV  100.0f
#define NPTS   8388608.0

__device__ double g_partials[NBLOCKS];

// x-derivatives (tgrad and tgrad∘tgrad) for the 4 points of the center float4.
// E0..E7 = values at x0-2 .. x0+5.
__device__ __forceinline__ void xder(float E0, float E1, float E2, float E3,
                                     float E4, float E5, float E6, float E7,
                                     int tid, float* dx, float* dxx)
{
    if (tid == 0) {
        dx[0]  = E3 - E2;
        dx[1]  = 0.5f * (E4 - E2);
        dxx[0] = 0.5f * E4 - E3 + 0.5f * E2;
        dxx[1] = 0.25f * E5 - 0.75f * E3 + 0.5f * E2;
    } else {
        dx[0]  = 0.5f * (E3 - E1);
        dx[1]  = 0.5f * (E4 - E2);
        dxx[0] = 0.25f * (E4 - 2.0f * E2 + E0);
        dxx[1] = 0.25f * (E5 - 2.0f * E3 + E1);
    }
    if (tid == 255) {
        dx[2]  = 0.5f * (E5 - E3);
        dx[3]  = E5 - E4;
        dxx[2] = 0.5f * E5 - 0.75f * E4 + 0.25f * E2;
        dxx[3] = 0.5f * E5 - E4 + 0.5f * E3;
    } else {
        dx[2]  = 0.5f * (E5 - E3);
        dx[3]  = 0.5f * (E6 - E4);
        dxx[2] = 0.25f * (E6 - 2.0f * E4 + E2);
        dxx[3] = 0.25f * (E7 - 2.0f * E5 + E3);
    }
}

// Full derivative set for one channel from its smem circular buffer.
__device__ __forceinline__ void chan_derivs(
    const float* __restrict__ s,
    int sm2, int sm1, int sc, int sp1, int sp2,
    int tid, int x0,
    float s1, float cm2, float cm1, float cc, float cp1, float cp2,
    float* v, float* dx, float* dxx, float* dy, float* dyy)
{
    float4 c = *(const float4*)&s[sc * NX + x0];
    float2 L = make_float2(0.0f, 0.0f), R = make_float2(0.0f, 0.0f);
    if (tid > 0)   L = *(const float2*)&s[sc * NX + x0 - 2];
    if (tid < 255) R = *(const float2*)&s[sc * NX + x0 + 4];
    xder(L.x, L.y, c.x, c.y, c.z, c.w, R.x, R.y, tid, dx, dxx);

    float4 m1 = *(const float4*)&s[sm1 * NX + x0];
    float4 q1 = *(const float4*)&s[sp1 * NX + x0];
    float4 m2 = *(const float4*)&s[sm2 * NX + x0];
    float4 q2 = *(const float4*)&s[sp2 * NX + x0];
    const float* C  = (const float*)&c;
    const float* M1 = (const float*)&m1; const float* Q1 = (const float*)&q1;
    const float* M2 = (const float*)&m2; const float* Q2 = (const float*)&q2;
#pragma unroll
    for (int j = 0; j < 4; j++) {
        v[j]   = C[j];
        dy[j]  = s1 * (Q1[j] - M1[j]);
        dyy[j] = cm2 * M2[j] + cm1 * M1[j] + cc * C[j] + cp1 * Q1[j] + cp2 * Q2[j];
    }
}

__global__ __launch_bounds__(256, 3)
void physics_loss_kernel(const float* __restrict__ fno, const float* __restrict__ fne)
{
    extern __shared__ float sm[];
    float* sU = sm;
    float* sV = sm + 5 * NX;
    float* sT = sm + 10 * NX;
    float* sP = sm + 15 * NX;

    const int tid   = threadIdx.x;
    const int strip = blockIdx.x;
    const int b     = blockIdx.y;
    const int y0    = strip * ROWS;
    const int x0    = tid * 4;

    const size_t base = (size_t)b * 4 * CH;
    const float* __restrict__ Uc = fne + base;
    const float* __restrict__ Vc = fne + base + CH;
    const float* __restrict__ Tc = fne + base + 2 * (size_t)CH;
    const float* __restrict__ Pc = fne + base + 3 * (size_t)CH;
    const float* __restrict__ Uo_c = fno + base;
    const float* __restrict__ Vo_c = fno + base + CH;
    const float* __restrict__ To_c = fno + base + 2 * (size_t)CH;

    auto ld4 = [&](const float* __restrict__ chp, int y) -> float4 {
        y = max(0, min(y, NY - 1));
        return *(const float4*)(chp + (size_t)y * NX + x0);
    };

    // prologue: fill circular buffers (rows y0-2..y0+2 for UVT, y0-1..y0+1 for P)
#pragma unroll
    for (int k = -2; k <= 2; k++) {
        int slot = (y0 + k + 10) % 5;
        float4 a = ld4(Uc, y0 + k);
        float4 bb = ld4(Vc, y0 + k);
        float4 cc4 = ld4(Tc, y0 + k);
        *(float4*)&sU[slot * NX + x0] = a;
        *(float4*)&sV[slot * NX + x0] = bb;
        *(float4*)&sT[slot * NX + x0] = cc4;
    }
#pragma unroll
    for (int k = -1; k <= 1; k++) {
        int slot = (y0 + k + 9) % 3;
        *(float4*)&sP[slot * NX + x0] = ld4(Pc, y0 + k);
    }
    __syncthreads();

    double dacc = 0.0;

    for (int y = y0; y < y0 + ROWS; y++) {
        // prefetch next rows (GMEM latency hidden under smem compute)
        float4 nu = ld4(Uc, y + 3);
        float4 nv = ld4(Vc, y + 3);
        float4 nt = ld4(Tc, y + 3);
        float4 np = ld4(Pc, y + 2);
        const size_t ro = (size_t)y * NX + x0;
        float4 uo4 = *(const float4*)(Uo_c + ro);
        float4 vo4 = *(const float4*)(Vo_c + ro);
        float4 to4 = *(const float4*)(To_c + ro);

        // circular slots for rows y-2..y+2 (UVT) and y-1..y+1 (P)
        const int sm2 = (y + 8) % 5, sm1 = (y + 9) % 5, sc = (y + 10) % 5,
                  sp1 = (y + 11) % 5, sp2 = (y + 12) % 5;
        const int pm1 = (y + 8) % 3, pc = (y + 9) % 3, pp1 = (y + 10) % 3;

        // y-derivative coefficients
        const float s1 = (y == 0 || y == NY - 1) ? 1.0f : 0.5f;
        float cm2, cm1, cc, cp1, cp2;
        if      (y == 0)      { cm2 = 0;     cm1 = 0;     cc = 0.5f;   cp1 = -1.0f; cp2 = 0.5f; }
        else if (y == 1)      { cm2 = 0;     cm1 = 0.5f;  cc = -0.75f; cp1 = 0;     cp2 = 0.25f; }
        else if (y == NY - 2) { cm2 = 0.25f; cm1 = 0;     cc = -0.75f; cp1 = 0.5f;  cp2 = 0; }
        else if (y == NY - 1) { cm2 = 0.5f;  cm1 = -1.0f; cc = 0.5f;   cp1 = 0;     cp2 = 0; }
        else                  { cm2 = 0.25f; cm1 = 0;     cc = -0.5f;  cp1 = 0;     cp2 = 0.25f; }

        const float* UO = (const float*)&uo4;
        const float* VO = (const float*)&vo4;
        const float* TO = (const float*)&to4;

        float cont[4], resx[4], resy[4], rest[4];
        float v[4], dx[4], dxx[4], dy[4], dyy[4];

        // ---- U ----
        chan_derivs(sU, sm2, sm1, sc, sp1, sp2, tid, x0, s1, cm2, cm1, cc, cp1, cp2,
                    v, dx, dxx, dy, dyy);
#pragma unroll
        for (int j = 0; j < 4; j++) {
            float Un = v[j];
            cont[j] = dx[j];
            resx[j] = (Un - UO[j]) * DTINV + Un * dx[j] + VO[j] * dy[j]
                      - PR * (dxx[j] + dyy[j]) + PR_DA * Un;
        }
        // ---- V ----
        chan_derivs(sV, sm2, sm1, sc, sp1, sp2, tid, x0, s1, cm2, cm1, cc, cp1, cp2,
                    v, dx, dxx, dy, dyy);
#pragma unroll
        for (int j = 0; j < 4; j++) {
            float Vn = v[j];
            cont[j] += dy[j];
            resy[j] = (Vn - VO[j]) * DTINV + UO[j] * dx[j] + Vn * dy[j]
                      - PR * (dxx[j] + dyy[j]) + (HA2_PR + PR_DA) * Vn;
        }
        // ---- T ----
        chan_derivs(sT, sm2, sm1, sc, sp1, sp2, tid, x0, s1, cm2, cm1, cc, cp1, cp2,
                    v, dx, dxx, dy, dyy);
#pragma unroll
        for (int j = 0; j < 4; j++) {
            float Tn = v[j];
            resy[j] -= RA_PR * Tn;
            rest[j] = (Tn - TO[j]) * DTINV + UO[j] * dx[j] + VO[j] * dy[j]
                      - DIFF_C * (dxx[j] + dyy[j]) - QQ * Tn;
        }
        // ---- P (dx, dy only) ----
        {
            float4 c = *(const float4*)&sP[pc * NX + x0];
            float2 L = make_float2(0.0f, 0.0f), R = make_float2(0.0f, 0.0f);
            if (tid > 0)   L = *(const float2*)&sP[pc * NX + x0 - 2];
            if (tid < 255) R = *(const float2*)&sP[pc * NX + x0 + 4];
            float pdx[4], pdxx[4];
            xder(L.x, L.y, c.x, c.y, c.z, c.w, R.x, R.y, tid, pdx, pdxx);
            float4 m1 = *(const float4*)&sP[pm1 * NX + x0];
            float4 q1 = *(const float4*)&sP[pp1 * NX + x0];
            const float* M1 = (const float*)&m1;
            const float* Q1 = (const float*)&q1;
#pragma unroll
            for (int j = 0; j < 4; j++) {
                resx[j] += pdx[j];
                resy[j] += s1 * (Q1[j] - M1[j]);
            }
        }

        float rowacc = 0.0f;
#pragma unroll
        for (int j = 0; j < 4; j++)
            rowacc += cont[j] * cont[j] + resx[j] * resx[j]
                    + resy[j] * resy[j] + rest[j] * rest[j];
        dacc += (double)rowacc;

        __syncthreads();
        // store prefetched rows: slot(y+3) == sm2 (mod 5), slotP(y+2) == pm1 (mod 3)
        *(float4*)&sU[sm2 * NX + x0] = nu;
        *(float4*)&sV[sm2 * NX + x0] = nv;
        *(float4*)&sT[sm2 * NX + x0] = nt;
        *(float4*)&sP[pm1 * NX + x0] = np;
        __syncthreads();
    }

    // block reduction
#pragma unroll
    for (int o = 16; o > 0; o >>= 1)
        dacc += __shfl_xor_sync(0xFFFFFFFFu, dacc, o);

    __shared__ double ws[8];
    if ((tid & 31) == 0) ws[tid >> 5] = dacc;
    __syncthreads();
    if (tid == 0) {
        double s = 0.0;
#pragma unroll
        for (int k = 0; k < 8; k++) s += ws[k];
        g_partials[(size_t)b * STRIPS + strip] = s;
    }
}

__global__ __launch_bounds__(512)
void finalize_kernel(float* __restrict__ out)
{
    const int tid = threadIdx.x;
    double v = g_partials[tid];        // NBLOCKS == 512 == blockDim
#pragma unroll
    for (int o = 16; o > 0; o >>= 1)
        v += __shfl_xor_sync(0xFFFFFFFFu, v, o);
    __shared__ double ws[16];
    if ((tid & 31) == 0) ws[tid >> 5] = v;
    __syncthreads();
    if (tid == 0) {
        double s = 0.0;
#pragma unroll
        for (int k = 0; k < 16; k++) s += ws[k];
        double t = s * 1e-4 / NPTS;
        if (t < 1e-10) t = 1e-10;
        if (t > 1.0)   t = 1.0;
        out[0] = (float)t;
    }
}

extern "C" void kernel_launch(void* const* d_in, const int* in_sizes, int n_in,
                              void* d_out, int out_size)
{
    const float* f_now  = (const float*)d_in[0];
    const float* f_next = (const float*)d_in[1];

    cudaFuncSetAttribute(physics_loss_kernel,
                         cudaFuncAttributeMaxDynamicSharedMemorySize, SMEM_BYTES);

    dim3 grid(STRIPS, NB);
    physics_loss_kernel<<<grid, 256, SMEM_BYTES>>>(f_now, f_next);
    finalize_kernel<<<1, 512>>>((float*)d_out);
}